// round 4
// baseline (speedup 1.0000x reference)
#include <cuda_runtime.h>
#include <cuda_bf16.h>
#include <math.h>

#define NEG_INF_F (-1e30f)

static constexpr int B = 64;
static constexpr int C = 1024;
static constexpr int Q = 128;
static constexpr int H = 512;
static constexpr int NCH = 32;          // softmax_c chunks (C/NCH = 32 rows each)

// ---------------- scratch (device globals: allocation-free rule) ----------------
__device__ float g_qw[(size_t)B * Q * H];
__device__ float g_sub0[B * Q];
__device__ float g_sub1[B * C];
__device__ float g_S[(size_t)B * C * Q];
__device__ float g_Sc[(size_t)B * C * Q];
__device__ float g_tmp[(size_t)B * Q * H];
__device__ float g_pm[B * NCH * Q];
__device__ float g_ps[B * NCH * Q];
__device__ float g_gm[B * Q];
__device__ float g_ginv[B * Q];

// ---------------- helpers ----------------
__device__ __forceinline__ float to_tf32(float x) {
    asm("cvt.rna.tf32.f32 %0, %1;" : "=f"(x) : "f"(x));
    return x;
}

__device__ __forceinline__ void mma_tf32(float* c, const unsigned* a, const unsigned* b) {
    asm volatile(
        "mma.sync.aligned.m16n8k8.row.col.f32.tf32.tf32.f32 "
        "{%0,%1,%2,%3}, {%4,%5,%6,%7}, {%8,%9}, {%0,%1,%2,%3};"
        : "+f"(c[0]), "+f"(c[1]), "+f"(c[2]), "+f"(c[3])
        : "r"(a[0]), "r"(a[1]), "r"(a[2]), "r"(a[3]), "r"(b[0]), "r"(b[1]));
}

__device__ __forceinline__ float block_reduce_sum_128(float v, float* red) {
    int t = threadIdx.x;
    #pragma unroll
    for (int o = 16; o > 0; o >>= 1) v += __shfl_xor_sync(0xffffffffu, v, o);
    if ((t & 31) == 0) red[t >> 5] = v;
    __syncthreads();
    return red[0] + red[1] + red[2] + red[3];
}

// ---------------- prep kernels ----------------
__global__ void prep_query_kernel(const float* __restrict__ xq,
                                  const float* __restrict__ W0,
                                  const float* __restrict__ W2,
                                  float* __restrict__ qw,
                                  float* __restrict__ sub0) {
    int bq = blockIdx.x;
    int t = threadIdx.x;
    const float* row = xq + (size_t)bq * H;
    float* orow = qw + (size_t)bq * H;
    float s = 0.f;
    #pragma unroll
    for (int i = 0; i < H / 128; i++) {
        int h = i * 128 + t;
        float v = row[h];
        orow[h] = v * W2[h];
        s = fmaf(v, W0[h], s);
    }
    __shared__ float red[4];
    s = block_reduce_sum_128(s, red);
    if (t == 0) sub0[bq] = s;
}

__global__ void prep_context_kernel(const float* __restrict__ xc,
                                    const float* __restrict__ W1,
                                    float* __restrict__ sub1) {
    int bc = blockIdx.x;
    int t = threadIdx.x;
    const float* row = xc + (size_t)bc * H;
    float s = 0.f;
    #pragma unroll
    for (int i = 0; i < H / 128; i++) {
        int h = i * 128 + t;
        s = fmaf(row[h], W1[h], s);
    }
    __shared__ float red[4];
    s = block_reduce_sum_128(s, red);
    if (t == 0) sub1[bc] = s;
}

// ---------------- tf32 tensor-core batched GEMM (pipelined, pair-layout smem) ----------------
// D[m,n] = sum_k A(m,k)*B(n,k) (+rowBias[m] + colBias[n] + *scalarBias)
// AMODE 0: A row-major MxK; AMODE 1: A row-major KxM. Same for BMODE over N/K.
// Tile 128x128x16, 8 warps, warp tile 64x32. Double-buffered smem.
// Smem pair layout: s[ks][r][ (k&3)*2 + ((k>>2)&1) ] holds element (r, ks*8+kk);
// a fragment (k=tg, k=tg+4) is then ONE float2 at [r][tg*2].
template <int AMODE, int BMODE>
__global__ void __launch_bounds__(256, 2)
gemm_tf32_kernel(const float* __restrict__ A, const float* __restrict__ Bp,
                 float* __restrict__ Cp, int K,
                 int lda, int ldb, int ldc,
                 size_t sA, size_t sB, size_t sC,
                 const float* __restrict__ rowBias, int rbStride,
                 const float* __restrict__ colBias, int cbStride,
                 const float* __restrict__ scalarBias) {
    __shared__ float As2[2][2][128][8];   // [stage][ks][m][slot]
    __shared__ float Bs2[2][2][128][8];   // [stage][ks][n][slot]

    const int bz = blockIdx.z;
    A  += (size_t)bz * sA;
    Bp += (size_t)bz * sB;
    Cp += (size_t)bz * sC;
    const int tileM = blockIdx.y * 128;
    const int tileN = blockIdx.x * 128;
    const int tid = threadIdx.x;
    const int wid = tid >> 5, lane = tid & 31;
    const int warpM = (wid & 1) * 64;
    const int warpN = (wid >> 1) * 32;
    const int g = lane >> 2, tg = lane & 3;

    // staging index precompute (2 float4 per operand per iter)
    int am[2], ak[2], bn[2], bk[2];
    #pragma unroll
    for (int t = 0; t < 2; t++) {
        int i = tid + t * 256;
        if (AMODE == 0) { am[t] = i >> 2;  ak[t] = (i & 3) * 4; }
        else            { ak[t] = i >> 5;  am[t] = (i & 31) * 4; }
        if (BMODE == 0) { bn[t] = i >> 2;  bk[t] = (i & 3) * 4; }
        else            { bk[t] = i >> 5;  bn[t] = (i & 31) * 4; }
    }

    float4 ra[2], rb[2];
    auto ldgA = [&](int k0) {
        #pragma unroll
        for (int t = 0; t < 2; t++)
            ra[t] = (AMODE == 0)
                ? *(const float4*)(A + (size_t)(tileM + am[t]) * lda + k0 + ak[t])
                : *(const float4*)(A + (size_t)(k0 + ak[t]) * lda + tileM + am[t]);
    };
    auto ldgB = [&](int k0) {
        #pragma unroll
        for (int t = 0; t < 2; t++)
            rb[t] = (BMODE == 0)
                ? *(const float4*)(Bp + (size_t)(tileN + bn[t]) * ldb + k0 + bk[t])
                : *(const float4*)(Bp + (size_t)(k0 + bk[t]) * ldb + tileN + bn[t]);
    };
    auto stsAB = [&](int st) {
        #pragma unroll
        for (int t = 0; t < 2; t++) {
            float va[4] = {ra[t].x, ra[t].y, ra[t].z, ra[t].w};
            float vb[4] = {rb[t].x, rb[t].y, rb[t].z, rb[t].w};
            #pragma unroll
            for (int j = 0; j < 4; j++) {
                if (AMODE == 0) {
                    int k = ak[t] + j;
                    As2[st][(k >> 3) & 1][am[t]][(k & 3) * 2 + ((k >> 2) & 1)] = to_tf32(va[j]);
                } else {
                    int k = ak[t];
                    As2[st][(k >> 3) & 1][am[t] + j][(k & 3) * 2 + ((k >> 2) & 1)] = to_tf32(va[j]);
                }
                if (BMODE == 0) {
                    int k = bk[t] + j;
                    Bs2[st][(k >> 3) & 1][bn[t]][(k & 3) * 2 + ((k >> 2) & 1)] = to_tf32(vb[j]);
                } else {
                    int k = bk[t];
                    Bs2[st][(k >> 3) & 1][bn[t] + j][(k & 3) * 2 + ((k >> 2) & 1)] = to_tf32(vb[j]);
                }
            }
        }
    };

    float acc[4][4][4] = {};
    const int nIter = K >> 4;

    ldgA(0); ldgB(0);
    stsAB(0);
    int st = 0;

    for (int it = 0; it < nIter; it++) {
        __syncthreads();
        bool more = (it + 1) < nIter;
        if (more) { ldgA((it + 1) << 4); ldgB((it + 1) << 4); }

        #pragma unroll
        for (int ks = 0; ks < 2; ks++) {
            float2 a2[4][2];
            float2 b2[4];
            #pragma unroll
            for (int mt = 0; mt < 4; mt++) {
                int m0 = warpM + mt * 16 + g;
                a2[mt][0] = *(const float2*)&As2[st][ks][m0    ][tg * 2];
                a2[mt][1] = *(const float2*)&As2[st][ks][m0 + 8][tg * 2];
            }
            #pragma unroll
            for (int nt = 0; nt < 4; nt++)
                b2[nt] = *(const float2*)&Bs2[st][ks][warpN + nt * 8 + g][tg * 2];
            #pragma unroll
            for (int mt = 0; mt < 4; mt++) {
                unsigned af[4] = {__float_as_uint(a2[mt][0].x), __float_as_uint(a2[mt][1].x),
                                  __float_as_uint(a2[mt][0].y), __float_as_uint(a2[mt][1].y)};
                #pragma unroll
                for (int nt = 0; nt < 4; nt++) {
                    unsigned bf[2] = {__float_as_uint(b2[nt].x), __float_as_uint(b2[nt].y)};
                    mma_tf32(acc[mt][nt], af, bf);
                }
            }
        }
        if (more) stsAB(st ^ 1);
        st ^= 1;
    }

    // ---- epilogue ----
    const float sb = scalarBias ? __ldg(scalarBias) : 0.f;
    #pragma unroll
    for (int mt = 0; mt < 4; mt++) {
        int r0 = tileM + warpM + mt * 16 + g;
        int r1 = r0 + 8;
        float rb0 = rowBias ? rowBias[bz * rbStride + r0] + sb : sb;
        float rb1 = rowBias ? rowBias[bz * rbStride + r1] + sb : sb;
        #pragma unroll
        for (int nt = 0; nt < 4; nt++) {
            int c0 = tileN + warpN + nt * 8 + tg * 2;
            float cb0 = colBias ? colBias[bz * cbStride + c0    ] : 0.f;
            float cb1 = colBias ? colBias[bz * cbStride + c0 + 1] : 0.f;
            Cp[(size_t)r0 * ldc + c0    ] = acc[mt][nt][0] + rb0 + cb0;
            Cp[(size_t)r0 * ldc + c0 + 1] = acc[mt][nt][1] + rb0 + cb1;
            Cp[(size_t)r1 * ldc + c0    ] = acc[mt][nt][2] + rb1 + cb0;
            Cp[(size_t)r1 * ldc + c0 + 1] = acc[mt][nt][3] + rb1 + cb1;
        }
    }
}

// ---------------- softmax over c (axis=1): partial + combine ----------------
__global__ void softc_partial(const float* __restrict__ S,
                              const float* __restrict__ cmask,
                              float* __restrict__ pm, float* __restrict__ ps) {
    int chunk = blockIdx.x, b = blockIdx.y;
    int q = threadIdx.x;
    constexpr int RB = C / NCH;
    const float* Sb = S + ((size_t)b * C + chunk * RB) * Q + q;
    const float* mcb = cmask + (size_t)b * C + chunk * RB;
    float m = -INFINITY, s = 0.f;
    #pragma unroll 4
    for (int c = 0; c < RB; c++) {
        float v = Sb[(size_t)c * Q] + (1.f - mcb[c]) * NEG_INF_F;
        float mn = fmaxf(m, v);
        s = s * __expf(m - mn) + __expf(v - mn);
        m = mn;
    }
    pm[(b * NCH + chunk) * Q + q] = m;
    ps[(b * NCH + chunk) * Q + q] = s;
}

__global__ void softc_combine(const float* __restrict__ pm,
                              const float* __restrict__ ps,
                              float* __restrict__ gm, float* __restrict__ ginv) {
    int b = blockIdx.x, q = threadIdx.x;
    float m = -INFINITY;
    #pragma unroll
    for (int ch = 0; ch < NCH; ch++)
        m = fmaxf(m, pm[(b * NCH + ch) * Q + q]);
    float s = 0.f;
    #pragma unroll
    for (int ch = 0; ch < NCH; ch++)
        s += ps[(b * NCH + ch) * Q + q] * __expf(pm[(b * NCH + ch) * Q + q] - m);
    gm[b * Q + q] = m;
    ginv[b * Q + q] = 1.f / s;
}

// ---------------- fused: softmax_q (in place on S) + softc write (to Sc) ----------------
// warp per c-row; one read of S serves both outputs.
__global__ void fused_post(float* __restrict__ S,
                           float* __restrict__ Sc,
                           const float* __restrict__ cmask,
                           const float* __restrict__ qmask,
                           const float* __restrict__ gm,
                           const float* __restrict__ ginv) {
    int b = blockIdx.y;
    int c = blockIdx.x * 8 + (threadIdx.x >> 5);
    int lane = threadIdx.x & 31;
    size_t base = ((size_t)b * C + c) * Q;
    float cadd = (1.f - cmask[b * C + c]) * NEG_INF_F;

    float raw[4], v[4];
    #pragma unroll
    for (int i = 0; i < 4; i++) {
        int q = lane + i * 32;
        raw[i] = S[base + q];
        v[i] = raw[i] + (1.f - qmask[b * Q + q]) * NEG_INF_F;
    }
    float m = fmaxf(fmaxf(v[0], v[1]), fmaxf(v[2], v[3]));
    #pragma unroll
    for (int o = 16; o > 0; o >>= 1) m = fmaxf(m, __shfl_xor_sync(0xffffffffu, m, o));
    float s = 0.f;
    #pragma unroll
    for (int i = 0; i < 4; i++) { v[i] = __expf(v[i] - m); s += v[i]; }
    #pragma unroll
    for (int o = 16; o > 0; o >>= 1) s += __shfl_xor_sync(0xffffffffu, s, o);
    float inv = 1.f / s;
    #pragma unroll
    for (int i = 0; i < 4; i++) {
        int q = lane + i * 32;
        S[base + q]  = v[i] * inv;
        Sc[base + q] = __expf(raw[i] + cadd - gm[b * Q + q]) * ginv[b * Q + q];
    }
}

// ---------------- launch ----------------
extern "C" void kernel_launch(void* const* d_in, const int* in_sizes, int n_in,
                              void* d_out, int out_size) {
    const float* x_context    = (const float*)d_in[0];  // B,C,H
    const float* x_query      = (const float*)d_in[1];  // B,Q,H
    const float* context_mask = (const float*)d_in[2];  // B,C
    const float* query_mask   = (const float*)d_in[3];  // B,Q
    const float* W0           = (const float*)d_in[4];
    const float* W1           = (const float*)d_in[5];
    const float* W2           = (const float*)d_in[6];
    const float* bias         = (const float*)d_in[7];
    float* out = (float*)d_out;                          // [c2q | q2c], each B*C*H

    float *p_qw, *p_sub0, *p_sub1, *p_S, *p_Sc, *p_tmp, *p_pm, *p_ps, *p_gm, *p_ginv;
    cudaGetSymbolAddress((void**)&p_qw,   g_qw);
    cudaGetSymbolAddress((void**)&p_sub0, g_sub0);
    cudaGetSymbolAddress((void**)&p_sub1, g_sub1);
    cudaGetSymbolAddress((void**)&p_S,    g_S);
    cudaGetSymbolAddress((void**)&p_Sc,   g_Sc);
    cudaGetSymbolAddress((void**)&p_tmp,  g_tmp);
    cudaGetSymbolAddress((void**)&p_pm,   g_pm);
    cudaGetSymbolAddress((void**)&p_ps,   g_ps);
    cudaGetSymbolAddress((void**)&p_gm,   g_gm);
    cudaGetSymbolAddress((void**)&p_ginv, g_ginv);

    const size_t BCH = (size_t)B * C * H;

    // 1. prep
    prep_query_kernel<<<B * Q, 128>>>(x_query, W0, W2, p_qw, p_sub0);
    prep_context_kernel<<<B * C, 128>>>(x_context, W1, p_sub1);

    // 2. S = Xc @ (Xq*W2)^T + sub1[c] + sub0[q] + bias
    gemm_tf32_kernel<0, 0><<<dim3(Q / 128, C / 128, B), 256>>>(
        x_context, p_qw, p_S, H, H, H, Q,
        (size_t)C * H, (size_t)Q * H, (size_t)C * Q,
        p_sub1, C, p_sub0, Q, bias);

    // 3. softmaxes: partial/combine over c, then fused write (Sc) + softmax_q (S in place)
    softc_partial<<<dim3(NCH, B), Q>>>(p_S, context_mask, p_pm, p_ps);
    softc_combine<<<B, Q>>>(p_pm, p_ps, p_gm, p_ginv);
    fused_post<<<dim3(C / 8, B), 256>>>(p_S, p_Sc, context_mask, query_mask, p_gm, p_ginv);

    // 4. tmp = S_c^T @ Xc   (M=Q, N=H, K=C)
    gemm_tf32_kernel<1, 1><<<dim3(H / 128, Q / 128, B), 256>>>(
        p_Sc, x_context, p_tmp, C, Q, H, H,
        (size_t)C * Q, (size_t)C * H, (size_t)Q * H,
        nullptr, 0, nullptr, 0, nullptr);

    // 5. c2q = S_ @ Xq   (M=C, N=H, K=Q)
    gemm_tf32_kernel<0, 1><<<dim3(H / 128, C / 128, B), 256>>>(
        p_S, x_query, out, Q, Q, H, H,
        (size_t)C * Q, (size_t)Q * H, (size_t)C * H,
        nullptr, 0, nullptr, 0, nullptr);

    // 6. q2c = S_ @ tmp  (M=C, N=H, K=Q)
    gemm_tf32_kernel<0, 1><<<dim3(H / 128, C / 128, B), 256>>>(
        p_S, p_tmp, out + BCH, Q, Q, H, H,
        (size_t)C * Q, (size_t)Q * H, (size_t)C * H,
        nullptr, 0, nullptr, 0, nullptr);
}

// round 5
// speedup vs baseline: 2.0062x; 2.0062x over previous
#include <cuda_runtime.h>
#include <cuda_bf16.h>
#include <math.h>

#define NEG_INF_F (-1e30f)

static constexpr int B = 64;
static constexpr int C = 1024;
static constexpr int Q = 128;
static constexpr int H = 512;
static constexpr int NCH = 32;

// ---------------- scratch (device globals: allocation-free rule) ----------------
__device__ float g_qw[(size_t)B * Q * H];
__device__ float g_sub0[B * Q];
__device__ float g_sub1[B * C];
__device__ float g_S[(size_t)B * C * Q];
__device__ float g_Sc[(size_t)B * C * Q];
__device__ float g_tmp[(size_t)B * Q * H];
__device__ float g_pm[B * NCH * Q];
__device__ float g_ps[B * NCH * Q];
__device__ float g_gm[B * Q];
__device__ float g_ginv[B * Q];

// ---------------- helpers ----------------
__device__ __forceinline__ float to_tf32(float x) {
    asm("cvt.rna.tf32.f32 %0, %1;" : "=f"(x) : "f"(x));
    return x;
}
__device__ __forceinline__ unsigned U32(float x) { return __float_as_uint(to_tf32(x)); }

__device__ __forceinline__ void mma_tf32(float* c, const unsigned* a, const unsigned* b) {
    asm volatile(
        "mma.sync.aligned.m16n8k8.row.col.f32.tf32.tf32.f32 "
        "{%0,%1,%2,%3}, {%4,%5,%6,%7}, {%8,%9}, {%0,%1,%2,%3};"
        : "+f"(c[0]), "+f"(c[1]), "+f"(c[2]), "+f"(c[3])
        : "r"(a[0]), "r"(a[1]), "r"(a[2]), "r"(a[3]), "r"(b[0]), "r"(b[1]));
}

__device__ __forceinline__ void cp16(unsigned s, const float* g) {
    asm volatile("cp.async.cg.shared.global [%0], [%1], 16;" :: "r"(s), "l"(g));
}
__device__ __forceinline__ void cp_commit() {
    asm volatile("cp.async.commit_group;" ::: "memory");
}
__device__ __forceinline__ void cp_wait2() {
    asm volatile("cp.async.wait_group 2;" ::: "memory");
}

__device__ __forceinline__ float block_reduce_sum_128(float v, float* red) {
    int t = threadIdx.x;
    #pragma unroll
    for (int o = 16; o > 0; o >>= 1) v += __shfl_xor_sync(0xffffffffu, v, o);
    if ((t & 31) == 0) red[t >> 5] = v;
    __syncthreads();
    return red[0] + red[1] + red[2] + red[3];
}

// ---------------- prep kernels ----------------
__global__ void prep_query_kernel(const float* __restrict__ xq,
                                  const float* __restrict__ W0,
                                  const float* __restrict__ W2,
                                  float* __restrict__ qw,
                                  float* __restrict__ sub0) {
    int bq = blockIdx.x;
    int t = threadIdx.x;
    const float* row = xq + (size_t)bq * H;
    float* orow = qw + (size_t)bq * H;
    float s = 0.f;
    #pragma unroll
    for (int i = 0; i < H / 128; i++) {
        int h = i * 128 + t;
        float v = row[h];
        orow[h] = v * W2[h];
        s = fmaf(v, W0[h], s);
    }
    __shared__ float red[4];
    s = block_reduce_sum_128(s, red);
    if (t == 0) sub0[bq] = s;
}

__global__ void prep_context_kernel(const float* __restrict__ xc,
                                    const float* __restrict__ W1,
                                    float* __restrict__ sub1) {
    int bc = blockIdx.x;
    int t = threadIdx.x;
    const float* row = xc + (size_t)bc * H;
    float s = 0.f;
    #pragma unroll
    for (int i = 0; i < H / 128; i++) {
        int h = i * 128 + t;
        s = fmaf(row[h], W1[h], s);
    }
    __shared__ float red[4];
    s = block_reduce_sum_128(s, red);
    if (t == 0) sub1[bc] = s;
}

// ---------------- tf32 tensor-core batched GEMM: cp.async 4-stage pipeline ----------------
// D[m,n] = sum_k A(m,k)*B(n,k)  (+rowBias[m] + colBias[n] + *scalarBias)
// AMODE 0: A row-major MxK (tile in smem as [r][16], swizzle k^(((r>>1)&3)<<2))
// AMODE 1: A row-major KxM (tile in smem as [k][128], swizzle m^((k&3)<<3))
// Same for B over N/K. Tile 128x128x16, 8 warps, warp tile 64x32.
template <int AMODE, int BMODE>
__global__ void __launch_bounds__(256)
gemm_tf32_kernel(const float* __restrict__ A, const float* __restrict__ Bp,
                 float* __restrict__ Cp, int K,
                 int lda, int ldb, int ldc,
                 size_t sA, size_t sB, size_t sC,
                 const float* __restrict__ rowBias, int rbStride,
                 const float* __restrict__ colBias, int cbStride,
                 const float* __restrict__ scalarBias) {
    extern __shared__ float smem[];
    float* As = smem;                 // 4 stages x 2048 floats
    float* Bs = smem + 4 * 2048;      // 4 stages x 2048 floats

    const int bz = blockIdx.z;
    A  += (size_t)bz * sA;
    Bp += (size_t)bz * sB;
    Cp += (size_t)bz * sC;
    const int tileM = blockIdx.y * 128;
    const int tileN = blockIdx.x * 128;
    const int tid = threadIdx.x;
    const int wid = tid >> 5, lane = tid & 31;
    const int warpM = (wid & 1) * 64;
    const int warpN = (wid >> 1) * 32;
    const int g = lane >> 2, tg = lane & 3;

    const unsigned asBase = (unsigned)__cvta_generic_to_shared(As);
    const unsigned bsBase = (unsigned)__cvta_generic_to_shared(Bs);

    // cp.async chunk schedule: 512 16B-chunks per operand per iter, 2 per thread.
    unsigned aOff[2], bOff[2];        // smem word offsets within a stage
    const float* aG[2];
    const float* bG[2];
    const int aAdv = (AMODE == 0) ? 1 : lda;   // gmem advance per k0 unit
    const int bAdv = (BMODE == 0) ? 1 : ldb;
    #pragma unroll
    for (int t = 0; t < 2; t++) {
        int c = tid + t * 256;
        if (AMODE == 0) {
            int r = c >> 2, kc = (c & 3) * 4;
            aOff[t] = r * 16 + (kc ^ ((((r >> 1) & 3)) << 2));
            aG[t] = A + (size_t)(tileM + r) * lda + kc;
        } else {
            int k = c >> 5, mc = (c & 31) * 4;
            aOff[t] = k * 128 + (mc ^ ((k & 3) << 3));
            aG[t] = A + (size_t)k * lda + tileM + mc;
        }
        if (BMODE == 0) {
            int r = c >> 2, kc = (c & 3) * 4;
            bOff[t] = r * 16 + (kc ^ ((((r >> 1) & 3)) << 2));
            bG[t] = Bp + (size_t)(tileN + r) * ldb + kc;
        } else {
            int k = c >> 5, nc = (c & 31) * 4;
            bOff[t] = k * 128 + (nc ^ ((k & 3) << 3));
            bG[t] = Bp + (size_t)k * ldb + tileN + nc;
        }
    }

    auto prefetch = [&](int it, int st) {
        int k0 = it << 4;
        #pragma unroll
        for (int t = 0; t < 2; t++) {
            cp16(asBase + (unsigned)(st * 2048 + aOff[t]) * 4, aG[t] + (size_t)k0 * aAdv);
            cp16(bsBase + (unsigned)(st * 2048 + bOff[t]) * 4, bG[t] + (size_t)k0 * bAdv);
        }
    };

    // logical element accessors (swizzled)
    auto ldA = [&](int st, int m, int k) -> float {
        int idx = (AMODE == 0) ? m * 16 + (k ^ ((((m >> 1) & 3)) << 2))
                               : k * 128 + (m ^ ((k & 3) << 3));
        return As[st * 2048 + idx];
    };
    auto ldB = [&](int st, int n, int k) -> float {
        int idx = (BMODE == 0) ? n * 16 + (k ^ ((((n >> 1) & 3)) << 2))
                               : k * 128 + (n ^ ((k & 3) << 3));
        return Bs[st * 2048 + idx];
    };

    float acc[4][4][4] = {};
    const int nIter = K >> 4;

    prefetch(0, 0); cp_commit();
    prefetch(1, 1); cp_commit();

    for (int it = 0; it < nIter; it++) {
        const int st = it & 3;
        if (it + 2 < nIter) prefetch(it + 2, (it + 2) & 3);
        cp_commit();
        cp_wait2();
        __syncthreads();

        #pragma unroll
        for (int ks = 0; ks < 2; ks++) {
            const int kb = ks * 8;
            unsigned af[4][4], bf[4][2];
            #pragma unroll
            for (int mt = 0; mt < 4; mt++) {
                int m0 = warpM + mt * 16 + g;
                af[mt][0] = U32(ldA(st, m0,     kb + tg));
                af[mt][1] = U32(ldA(st, m0 + 8, kb + tg));
                af[mt][2] = U32(ldA(st, m0,     kb + tg + 4));
                af[mt][3] = U32(ldA(st, m0 + 8, kb + tg + 4));
            }
            #pragma unroll
            for (int nt = 0; nt < 4; nt++) {
                int n0 = warpN + nt * 8 + g;
                bf[nt][0] = U32(ldB(st, n0, kb + tg));
                bf[nt][1] = U32(ldB(st, n0, kb + tg + 4));
            }
            #pragma unroll
            for (int mt = 0; mt < 4; mt++)
                #pragma unroll
                for (int nt = 0; nt < 4; nt++)
                    mma_tf32(acc[mt][nt], af[mt], bf[nt]);
        }
    }

    // ---- epilogue ----
    const float sb = scalarBias ? __ldg(scalarBias) : 0.f;
    #pragma unroll
    for (int mt = 0; mt < 4; mt++) {
        int r0 = tileM + warpM + mt * 16 + g;
        int r1 = r0 + 8;
        float rb0 = rowBias ? rowBias[bz * rbStride + r0] + sb : sb;
        float rb1 = rowBias ? rowBias[bz * rbStride + r1] + sb : sb;
        #pragma unroll
        for (int nt = 0; nt < 4; nt++) {
            int c0 = tileN + warpN + nt * 8 + tg * 2;
            float cb0 = colBias ? colBias[bz * cbStride + c0    ] : 0.f;
            float cb1 = colBias ? colBias[bz * cbStride + c0 + 1] : 0.f;
            Cp[(size_t)r0 * ldc + c0    ] = acc[mt][nt][0] + rb0 + cb0;
            Cp[(size_t)r0 * ldc + c0 + 1] = acc[mt][nt][1] + rb0 + cb1;
            Cp[(size_t)r1 * ldc + c0    ] = acc[mt][nt][2] + rb1 + cb0;
            Cp[(size_t)r1 * ldc + c0 + 1] = acc[mt][nt][3] + rb1 + cb1;
        }
    }
}

// ---------------- softmax over c (axis=1): partial + combine ----------------
__global__ void softc_partial(const float* __restrict__ S,
                              const float* __restrict__ cmask,
                              float* __restrict__ pm, float* __restrict__ ps) {
    int chunk = blockIdx.x, b = blockIdx.y;
    int q = threadIdx.x;
    constexpr int RB = C / NCH;
    const float* Sb = S + ((size_t)b * C + chunk * RB) * Q + q;
    const float* mcb = cmask + (size_t)b * C + chunk * RB;
    float m = -INFINITY, s = 0.f;
    #pragma unroll 4
    for (int c = 0; c < RB; c++) {
        float v = Sb[(size_t)c * Q] + (1.f - mcb[c]) * NEG_INF_F;
        float mn = fmaxf(m, v);
        s = s * __expf(m - mn) + __expf(v - mn);
        m = mn;
    }
    pm[(b * NCH + chunk) * Q + q] = m;
    ps[(b * NCH + chunk) * Q + q] = s;
}

__global__ void softc_combine(const float* __restrict__ pm,
                              const float* __restrict__ ps,
                              float* __restrict__ gm, float* __restrict__ ginv) {
    int b = blockIdx.x, q = threadIdx.x;
    float m = -INFINITY;
    #pragma unroll
    for (int ch = 0; ch < NCH; ch++)
        m = fmaxf(m, pm[(b * NCH + ch) * Q + q]);
    float s = 0.f;
    #pragma unroll
    for (int ch = 0; ch < NCH; ch++)
        s += ps[(b * NCH + ch) * Q + q] * __expf(pm[(b * NCH + ch) * Q + q] - m);
    gm[b * Q + q] = m;
    ginv[b * Q + q] = 1.f / s;
}

// ---------------- fused: softmax_q (in place on S) + softc write (to Sc) ----------------
__global__ void fused_post(float* __restrict__ S,
                           float* __restrict__ Sc,
                           const float* __restrict__ cmask,
                           const float* __restrict__ qmask,
                           const float* __restrict__ gm,
                           const float* __restrict__ ginv) {
    int b = blockIdx.y;
    int c = blockIdx.x * 8 + (threadIdx.x >> 5);
    int lane = threadIdx.x & 31;
    size_t base = ((size_t)b * C + c) * Q;
    float cadd = (1.f - cmask[b * C + c]) * NEG_INF_F;

    float raw[4], v[4];
    #pragma unroll
    for (int i = 0; i < 4; i++) {
        int q = lane + i * 32;
        raw[i] = S[base + q];
        v[i] = raw[i] + (1.f - qmask[b * Q + q]) * NEG_INF_F;
    }
    float m = fmaxf(fmaxf(v[0], v[1]), fmaxf(v[2], v[3]));
    #pragma unroll
    for (int o = 16; o > 0; o >>= 1) m = fmaxf(m, __shfl_xor_sync(0xffffffffu, m, o));
    float s = 0.f;
    #pragma unroll
    for (int i = 0; i < 4; i++) { v[i] = __expf(v[i] - m); s += v[i]; }
    #pragma unroll
    for (int o = 16; o > 0; o >>= 1) s += __shfl_xor_sync(0xffffffffu, s, o);
    float inv = 1.f / s;
    #pragma unroll
    for (int i = 0; i < 4; i++) {
        int q = lane + i * 32;
        S[base + q]  = v[i] * inv;
        Sc[base + q] = __expf(raw[i] + cadd - gm[b * Q + q]) * ginv[b * Q + q];
    }
}

// ---------------- launch ----------------
extern "C" void kernel_launch(void* const* d_in, const int* in_sizes, int n_in,
                              void* d_out, int out_size) {
    const float* x_context    = (const float*)d_in[0];  // B,C,H
    const float* x_query      = (const float*)d_in[1];  // B,Q,H
    const float* context_mask = (const float*)d_in[2];  // B,C
    const float* query_mask   = (const float*)d_in[3];  // B,Q
    const float* W0           = (const float*)d_in[4];
    const float* W1           = (const float*)d_in[5];
    const float* W2           = (const float*)d_in[6];
    const float* bias         = (const float*)d_in[7];
    float* out = (float*)d_out;                          // [c2q | q2c], each B*C*H

    float *p_qw, *p_sub0, *p_sub1, *p_S, *p_Sc, *p_tmp, *p_pm, *p_ps, *p_gm, *p_ginv;
    cudaGetSymbolAddress((void**)&p_qw,   g_qw);
    cudaGetSymbolAddress((void**)&p_sub0, g_sub0);
    cudaGetSymbolAddress((void**)&p_sub1, g_sub1);
    cudaGetSymbolAddress((void**)&p_S,    g_S);
    cudaGetSymbolAddress((void**)&p_Sc,   g_Sc);
    cudaGetSymbolAddress((void**)&p_tmp,  g_tmp);
    cudaGetSymbolAddress((void**)&p_pm,   g_pm);
    cudaGetSymbolAddress((void**)&p_ps,   g_ps);
    cudaGetSymbolAddress((void**)&p_gm,   g_gm);
    cudaGetSymbolAddress((void**)&p_ginv, g_ginv);

    const size_t BCH = (size_t)B * C * H;
    const int SMEM = 4 * 2048 * 2 * sizeof(float);   // 64 KB

    cudaFuncSetAttribute(gemm_tf32_kernel<0, 0>, cudaFuncAttributeMaxDynamicSharedMemorySize, SMEM);
    cudaFuncSetAttribute(gemm_tf32_kernel<1, 1>, cudaFuncAttributeMaxDynamicSharedMemorySize, SMEM);
    cudaFuncSetAttribute(gemm_tf32_kernel<0, 1>, cudaFuncAttributeMaxDynamicSharedMemorySize, SMEM);

    // 1. prep
    prep_query_kernel<<<B * Q, 128>>>(x_query, W0, W2, p_qw, p_sub0);
    prep_context_kernel<<<B * C, 128>>>(x_context, W1, p_sub1);

    // 2. S = Xc @ (Xq*W2)^T + sub1[c] + sub0[q] + bias
    gemm_tf32_kernel<0, 0><<<dim3(Q / 128, C / 128, B), 256, SMEM>>>(
        x_context, p_qw, p_S, H, H, H, Q,
        (size_t)C * H, (size_t)Q * H, (size_t)C * Q,
        p_sub1, C, p_sub0, Q, bias);

    // 3. softmaxes
    softc_partial<<<dim3(NCH, B), Q>>>(p_S, context_mask, p_pm, p_ps);
    softc_combine<<<B, Q>>>(p_pm, p_ps, p_gm, p_ginv);
    fused_post<<<dim3(C / 8, B), 256>>>(p_S, p_Sc, context_mask, query_mask, p_gm, p_ginv);

    // 4. tmp = S_c^T @ Xc   (M=Q, N=H, K=C)
    gemm_tf32_kernel<1, 1><<<dim3(H / 128, Q / 128, B), 256, SMEM>>>(
        p_Sc, x_context, p_tmp, C, Q, H, H,
        (size_t)C * Q, (size_t)C * H, (size_t)Q * H,
        nullptr, 0, nullptr, 0, nullptr);

    // 5. c2q = S_ @ Xq   (M=C, N=H, K=Q)
    gemm_tf32_kernel<0, 1><<<dim3(H / 128, C / 128, B), 256, SMEM>>>(
        p_S, x_query, out, Q, Q, H, H,
        (size_t)C * Q, (size_t)Q * H, (size_t)C * H,
        nullptr, 0, nullptr, 0, nullptr);

    // 6. q2c = S_ @ tmp  (M=C, N=H, K=Q)
    gemm_tf32_kernel<0, 1><<<dim3(H / 128, C / 128, B), 256, SMEM>>>(
        p_S, p_tmp, out + BCH, Q, Q, H, H,
        (size_t)C * Q, (size_t)Q * H, (size_t)C * H,
        nullptr, 0, nullptr, 0, nullptr);
}